// round 10
// baseline (speedup 1.0000x reference)
#include <cuda_runtime.h>
#include <cstdint>
#include <math.h>

// ---------------- problem constants ----------------
#define BATCH 4
#define SEQ   2048
#define DIM   512
#define WIN   64
#define QT    32

// attention smem layout (D processed in 2 chunks of 256)
#define DC    256              // d-chunk width
#define TP2   260              // tile row pitch (floats); conflict-free LDS.128 phases
#define SROWS 96
#define SP    100              // score row pitch

// gemm tiling (mma.sync tf32 m16n8k8), fused K=1024
#define GM 128
#define GN 128
#define KC 32
#define NCHUNK (1024 / KC)     // 32
#define APADW 36               // A pitch [m][k]
#define BPW   36               // B pitch [n][k] (n-major for ldmatrix B-frags)
#define AFL (GM * APADW)       // 4608
#define BFL (GN * BPW)         // 4608
#define STF (AFL + BFL)        // 9216 floats per stage
#define NSTAGE 3

// context scratch [B*S, D] fp32 (no cudaMalloc allowed)
__device__ float g_c[BATCH * SEQ * DIM];

__device__ __forceinline__ uint32_t smem_u32(const void* p) {
    uint32_t a;
    asm("{ .reg .u64 t; cvta.to.shared.u64 t, %1; cvt.u32.u64 %0, t; }"
        : "=r"(a) : "l"(p));
    return a;
}
__device__ __forceinline__ void cpa16(uint32_t d, const float* s) {
    asm volatile("cp.async.cg.shared.global [%0], [%1], 16;" :: "r"(d), "l"(s));
}
__device__ __forceinline__ void cpa4(uint32_t d, const float* s) {
    asm volatile("cp.async.ca.shared.global [%0], [%1], 4;" :: "r"(d), "l"(s));
}
__device__ __forceinline__ void ldsm_x4(uint32_t& r0, uint32_t& r1,
                                        uint32_t& r2, uint32_t& r3, uint32_t addr) {
    asm volatile("ldmatrix.sync.aligned.m8n8.x4.shared.b16 {%0,%1,%2,%3}, [%4];"
                 : "=r"(r0), "=r"(r1), "=r"(r2), "=r"(r3) : "r"(addr));
}

extern __shared__ float sm_dyn[];

// ---------------------------------------------------------------------------
// Attention: 256 CTAs, 256 threads, QT=32 queries, 2 CTAs/SM.
// Dense phase 1 (R8, measured best). Phase 3 runs chunk 1 first (already
// resident from phase 1) -> 3 tile loads instead of 4.
// ---------------------------------------------------------------------------
__global__ __launch_bounds__(256, 2) void attn_kernel(const float* __restrict__ x) {
    float* tile = sm_dyn;                 // [96][TP2]
    float* S    = sm_dyn + SROWS * TP2;   // [32][SP]

    const int tid = threadIdx.x;
    const int b   = blockIdx.x >> 6;
    const int qs  = (blockIdx.x & 63) * QT;
    const float* xb = x + (size_t)b * SEQ * DIM;

    const int ty = tid >> 5;     // warp id (queries 4ty..4ty+3)
    const int tx = tid & 31;     // lane

    auto load_tile = [&](int d0) {
#pragma unroll 8
        for (int p = 0; p < 24; p++) {
            const int idx = tid + 256 * p;
            const int r   = idx >> 6;
            const int c4  = (idx & 63) << 2;
            const int gr  = qs - WIN + r;
            float4 v = make_float4(0.f, 0.f, 0.f, 0.f);
            if (gr >= 0)
                v = *reinterpret_cast<const float4*>(xb + (size_t)gr * DIM + d0 + c4);
            *reinterpret_cast<float4*>(tile + r * TP2 + c4) = v;
        }
    };

    // ---- phase 1: dense S[i][j] = <tile[64+i], tile[j]>, acc over 2 d-chunks ----
    float sa[4][3];
#pragma unroll
    for (int i = 0; i < 4; i++)
#pragma unroll
        for (int j = 0; j < 3; j++) sa[i][j] = 0.f;

#pragma unroll
    for (int ch = 0; ch < 2; ch++) {
        if (ch) __syncthreads();
        load_tile(ch * DC);
        __syncthreads();

        const float* q0 = tile + (WIN + 4 * ty) * TP2;
        const float* k0 = tile + tx * TP2;
#pragma unroll 2
        for (int d = 0; d < DC; d += 4) {
            float4 q[4], k[3];
#pragma unroll
            for (int ii = 0; ii < 4; ii++)
                q[ii] = *reinterpret_cast<const float4*>(q0 + ii * TP2 + d);
#pragma unroll
            for (int jj = 0; jj < 3; jj++)
                k[jj] = *reinterpret_cast<const float4*>(k0 + jj * 32 * TP2 + d);
#pragma unroll
            for (int ii = 0; ii < 4; ii++)
#pragma unroll
                for (int jj = 0; jj < 3; jj++) {
                    sa[ii][jj] = fmaf(q[ii].x, k[jj].x, sa[ii][jj]);
                    sa[ii][jj] = fmaf(q[ii].y, k[jj].y, sa[ii][jj]);
                    sa[ii][jj] = fmaf(q[ii].z, k[jj].z, sa[ii][jj]);
                    sa[ii][jj] = fmaf(q[ii].w, k[jj].w, sa[ii][jj]);
                }
        }
    }
#pragma unroll
    for (int ii = 0; ii < 4; ii++)
#pragma unroll
        for (int jj = 0; jj < 3; jj++)
            S[(4 * ty + ii) * SP + tx + 32 * jj] = sa[ii][jj];
    __syncthreads();

    // ---- phase 2: band softmax in-place -> dense alpha (zeros outside band) ----
    {
        const int i = tid >> 3;
        const int g = tid & 7;
        float* srow = S + i * SP;
        float m = -1e30f;
        float vals[8];
#pragma unroll
        for (int w8 = 0; w8 < 8; w8++) {
            vals[w8] = srow[i + g + 8 * w8];   // j = i + w, w in [0,64)
            m = fmaxf(m, vals[w8]);
        }
        m = fmaxf(m, __shfl_xor_sync(0xffffffffu, m, 1));
        m = fmaxf(m, __shfl_xor_sync(0xffffffffu, m, 2));
        m = fmaxf(m, __shfl_xor_sync(0xffffffffu, m, 4));
        float s = 0.f;
#pragma unroll
        for (int w8 = 0; w8 < 8; w8++) s += __expf(vals[w8] - m);
        s += __shfl_xor_sync(0xffffffffu, s, 1);
        s += __shfl_xor_sync(0xffffffffu, s, 2);
        s += __shfl_xor_sync(0xffffffffu, s, 4);
        const float inv = 1.f / s;
        __syncwarp();
#pragma unroll
        for (int jj = 0; jj < 12; jj++) {
            const int j = g * 12 + jj;
            float v = 0.f;
            if (j >= i && j < i + WIN) v = __expf(srow[j] - m) * inv;
            srow[j] = v;
        }
    }

    // ---- phase 3: chunk 1 first (resident), then chunk 0 ----
    const float* arow = S + 4 * ty * SP;
#pragma unroll
    for (int pass = 0; pass < 2; pass++) {
        const int ch = 1 - pass;
        __syncthreads();             // pass0: S visibility; pass1: done reading tile
        if (pass == 1) {
            load_tile(0);
            __syncthreads();
        }

        float cacc[4][8];
#pragma unroll
        for (int i = 0; i < 4; i++)
#pragma unroll
            for (int d = 0; d < 8; d++) cacc[i][d] = 0.f;

        for (int j = 0; j < 68; j++) {
            const int jj = 4 * ty + j;
            float a[4];
#pragma unroll
            for (int ii = 0; ii < 4; ii++) a[ii] = arow[ii * SP + jj];
            const float* kr = tile + jj * TP2 + 4 * tx;
#pragma unroll
            for (int q = 0; q < 2; q++) {
                float4 kv = *reinterpret_cast<const float4*>(kr + 128 * q);
#pragma unroll
                for (int ii = 0; ii < 4; ii++) {
                    cacc[ii][4 * q + 0] = fmaf(a[ii], kv.x, cacc[ii][4 * q + 0]);
                    cacc[ii][4 * q + 1] = fmaf(a[ii], kv.y, cacc[ii][4 * q + 1]);
                    cacc[ii][4 * q + 2] = fmaf(a[ii], kv.z, cacc[ii][4 * q + 2]);
                    cacc[ii][4 * q + 3] = fmaf(a[ii], kv.w, cacc[ii][4 * q + 3]);
                }
            }
        }
#pragma unroll
        for (int ii = 0; ii < 4; ii++) {
            float* crow = g_c + ((size_t)b * SEQ + qs + 4 * ty + ii) * DIM
                        + ch * DC + 4 * tx;
#pragma unroll
            for (int q = 0; q < 2; q++) {
                float4 v = make_float4(cacc[ii][4 * q], cacc[ii][4 * q + 1],
                                       cacc[ii][4 * q + 2], cacc[ii][4 * q + 3]);
                *reinterpret_cast<float4*>(crow + 128 * q) = v;
            }
        }
    }
}

// ---------------------------------------------------------------------------
// Output head: out = sigmoid([c | x] @ Wc) via mma.sync tf32 m16n8k8.
// CTA 128x128, 256 threads, warp tile 64x32, 3-stage cp.async.
// A-frags AND B-frags via ldmatrix.x4 (B stored n-major, pitch 36).
// ---------------------------------------------------------------------------
__device__ __forceinline__ void mma_tf32(float* c, uint32_t a0, uint32_t a1,
                                         uint32_t a2, uint32_t a3,
                                         uint32_t b0, uint32_t b1) {
    asm volatile(
        "mma.sync.aligned.m16n8k8.row.col.f32.tf32.tf32.f32 "
        "{%0,%1,%2,%3}, {%4,%5,%6,%7}, {%8,%9}, {%0,%1,%2,%3};"
        : "+f"(c[0]), "+f"(c[1]), "+f"(c[2]), "+f"(c[3])
        : "r"(a0), "r"(a1), "r"(a2), "r"(a3), "r"(b0), "r"(b1));
}

__device__ __forceinline__ void issue_chunk(int c, int bm, int bn, int tid,
                                            const float* __restrict__ x,
                                            const float* __restrict__ Wc) {
    float* Ad = sm_dyn + (c % NSTAGE) * STF;
    float* Bd = Ad + AFL;
    const float* Asrc = (c < 16) ? g_c : x;
    const int koff = (c < 16) ? c * KC : c * KC - 512;
    // A tile [m][k]: 128 rows x 32 floats, cp.async.16
#pragma unroll
    for (int p = 0; p < 4; p++) {
        const int idx = tid + 256 * p;
        const int r   = idx >> 3;
        const int seg = (idx & 7) * 4;
        cpa16(smem_u32(Ad + r * APADW + seg),
              Asrc + (size_t)(bm + r) * DIM + koff + seg);
    }
    // B tile [n][k]: 128 n-rows x 32 k; transpose-gather via cp.async.4.
    // Per warp-instruction k is fixed and n is 32 consecutive -> coalesced.
    {
        const int n      = tid & 127;
        const int khalf  = (tid >> 7) << 4;     // 0 or 16
        const float* wsrc = Wc + (size_t)(c * KC + khalf) * DIM + bn + n;
        uint32_t bdst = smem_u32(Bd + n * BPW + khalf);
#pragma unroll
        for (int kk2 = 0; kk2 < 16; kk2++)
            cpa4(bdst + 4u * kk2, wsrc + (size_t)kk2 * DIM);
    }
    asm volatile("cp.async.commit_group;" ::: "memory");
}

__global__ __launch_bounds__(256, 2) void gemm_mma(const float* __restrict__ x,
                                                   const float* __restrict__ Wc,
                                                   float* __restrict__ out) {
    const int tid  = threadIdx.x;
    const int wid  = tid >> 5;
    const int lane = tid & 31;
    const int gid  = lane >> 2;
    const int tig  = lane & 3;
    const int wm   = wid & 1;
    const int wn   = wid >> 1;
    const int bm   = blockIdx.y * GM;
    const int bn   = blockIdx.x * GN;

    float acc[4][4][4];
#pragma unroll
    for (int i = 0; i < 4; i++)
#pragma unroll
        for (int j = 0; j < 4; j++)
#pragma unroll
            for (int k = 0; k < 4; k++) acc[i][j][k] = 0.f;

    const uint32_t sm_base = smem_u32(sm_dyn);
    // A ldmatrix: row = wm*64 + ma*16 + (lane&15), col = kk + ((lane>=16)?4:0)
    const uint32_t a_lm_off =
        (uint32_t)(((wm * 64 + (lane & 15)) * APADW + ((lane >> 4) << 2)) * 4);
    // B ldmatrix: lane l supplies n-row wn*32 + l
    const uint32_t b_lm_off = (uint32_t)(((wn * 32 + lane) * BPW) * 4);

    issue_chunk(0, bm, bn, tid, x, Wc);
    issue_chunk(1, bm, bn, tid, x, Wc);

    for (int c = 0; c < NCHUNK; c++) {
        if (c == NCHUNK - 1)
            asm volatile("cp.async.wait_group 0;" ::: "memory");
        else
            asm volatile("cp.async.wait_group 1;" ::: "memory");
        __syncthreads();
        if (c + 2 < NCHUNK) issue_chunk(c + 2, bm, bn, tid, x, Wc);

        const uint32_t As_addr = sm_base + (uint32_t)((c % NSTAGE) * STF * 4);
        const uint32_t Bs_addr = As_addr + (uint32_t)(AFL * 4);
#pragma unroll
        for (int kk = 0; kk < KC; kk += 8) {
            uint32_t a[4][4], b0[4], b1[4];
#pragma unroll
            for (int ma = 0; ma < 4; ma++)
                ldsm_x4(a[ma][0], a[ma][1], a[ma][2], a[ma][3],
                        As_addr + a_lm_off + (uint32_t)((ma * 16 * APADW + kk) * 4));
            ldsm_x4(b0[0], b0[1], b0[2], b0[3],
                    Bs_addr + b_lm_off + (uint32_t)(kk * 4));
            ldsm_x4(b1[0], b1[1], b1[2], b1[3],
                    Bs_addr + b_lm_off + (uint32_t)((kk + 4) * 4));
#pragma unroll
            for (int ma = 0; ma < 4; ma++)
#pragma unroll
                for (int na = 0; na < 4; na++)
                    mma_tf32(acc[ma][na], a[ma][0], a[ma][1], a[ma][2], a[ma][3],
                             b0[na], b1[na]);
        }
    }

    // ---- epilogue: sigmoid + store ----
#pragma unroll
    for (int ma = 0; ma < 4; ma++) {
#pragma unroll
        for (int na = 0; na < 4; na++) {
            const int row = bm + wm * 64 + ma * 16 + gid;
            const int col = bn + wn * 32 + na * 8 + 2 * tig;
            float2 v0, v1;
            v0.x = 1.f / (1.f + __expf(-acc[ma][na][0]));
            v0.y = 1.f / (1.f + __expf(-acc[ma][na][1]));
            v1.x = 1.f / (1.f + __expf(-acc[ma][na][2]));
            v1.y = 1.f / (1.f + __expf(-acc[ma][na][3]));
            *reinterpret_cast<float2*>(out + (size_t)row * DIM + col) = v0;
            *reinterpret_cast<float2*>(out + (size_t)(row + 8) * DIM + col) = v1;
        }
    }
}

extern "C" void kernel_launch(void* const* d_in, const int* in_sizes, int n_in,
                              void* d_out, int out_size) {
    const float* x  = (const float*)d_in[0];   // (4, 2048, 512) fp32
    const float* Wc = (const float*)d_in[1];   // (1024, 512) fp32
    float* out = (float*)d_out;                // (4, 2048, 512) fp32

    const size_t attn_smem = (size_t)(SROWS * TP2 + QT * SP) * sizeof(float); // 112,640 B
    cudaFuncSetAttribute(attn_kernel, cudaFuncAttributeMaxDynamicSharedMemorySize,
                         (int)attn_smem);
    attn_kernel<<<BATCH * (SEQ / QT), 256, attn_smem>>>(x);

    const size_t gemm_smem = (size_t)(NSTAGE * STF) * sizeof(float);  // 110,592 B
    cudaFuncSetAttribute(gemm_mma, cudaFuncAttributeMaxDynamicSharedMemorySize,
                         (int)gemm_smem);
    dim3 grid(DIM / GN, (BATCH * SEQ) / GM);   // (4, 64)
    gemm_mma<<<grid, 256, gemm_smem>>>(x, Wc, out);
}

// round 11
// speedup vs baseline: 1.1606x; 1.1606x over previous
#include <cuda_runtime.h>
#include <cstdint>
#include <math.h>

// ---------------- problem constants ----------------
#define BATCH 4
#define SEQ   2048
#define DIM   512
#define WIN   64
#define QT    32

// attention smem layout (D processed in 2 chunks of 256)
#define DC    256              // d-chunk width
#define TP2   260              // tile row pitch (floats); conflict-free LDS.128 phases
#define SROWS 96
#define SP    100              // score row pitch

// gemm tiling (mma.sync tf32 m16n8k8), fused K=1024
#define GM 128
#define GN 128
#define KC 32
#define NCHUNK (1024 / KC)     // 32
#define APADW 36               // A pitch [m][k]
#define BPADW 136              // B pitch [k][n]; b-frag banks 8*tig+gid all distinct
#define AFL (GM * APADW)       // 4608
#define BFL (KC * BPADW)       // 4352
#define STF (AFL + BFL)        // 8960 floats per stage
#define NSTAGE 3

// context scratch [B*S, D] fp32 (no cudaMalloc allowed)
__device__ float g_c[BATCH * SEQ * DIM];

__device__ __forceinline__ uint32_t smem_u32(const void* p) {
    uint32_t a;
    asm("{ .reg .u64 t; cvta.to.shared.u64 t, %1; cvt.u32.u64 %0, t; }"
        : "=r"(a) : "l"(p));
    return a;
}
__device__ __forceinline__ void cpa16(uint32_t d, const float* s) {
    asm volatile("cp.async.cg.shared.global [%0], [%1], 16;" :: "r"(d), "l"(s));
}
__device__ __forceinline__ void ldsm_x4(uint32_t& r0, uint32_t& r1,
                                        uint32_t& r2, uint32_t& r3, uint32_t addr) {
    asm volatile("ldmatrix.sync.aligned.m8n8.x4.shared.b16 {%0,%1,%2,%3}, [%4];"
                 : "=r"(r0), "=r"(r1), "=r"(r2), "=r"(r3) : "r"(addr));
}

extern __shared__ float sm_dyn[];

// ---------------------------------------------------------------------------
// Attention: 256 CTAs, 256 threads, QT=32 queries, 2 CTAs/SM. (R10, 45.8us)
// Dense phase 1; phase 3 runs chunk 1 first (resident) -> 3 tile loads.
// ---------------------------------------------------------------------------
__global__ __launch_bounds__(256, 2) void attn_kernel(const float* __restrict__ x) {
    float* tile = sm_dyn;                 // [96][TP2]
    float* S    = sm_dyn + SROWS * TP2;   // [32][SP]

    const int tid = threadIdx.x;
    const int b   = blockIdx.x >> 6;
    const int qs  = (blockIdx.x & 63) * QT;
    const float* xb = x + (size_t)b * SEQ * DIM;

    const int ty = tid >> 5;     // warp id (queries 4ty..4ty+3)
    const int tx = tid & 31;     // lane

    auto load_tile = [&](int d0) {
#pragma unroll 8
        for (int p = 0; p < 24; p++) {
            const int idx = tid + 256 * p;
            const int r   = idx >> 6;
            const int c4  = (idx & 63) << 2;
            const int gr  = qs - WIN + r;
            float4 v = make_float4(0.f, 0.f, 0.f, 0.f);
            if (gr >= 0)
                v = *reinterpret_cast<const float4*>(xb + (size_t)gr * DIM + d0 + c4);
            *reinterpret_cast<float4*>(tile + r * TP2 + c4) = v;
        }
    };

    // ---- phase 1: dense S[i][j] = <tile[64+i], tile[j]>, acc over 2 d-chunks ----
    float sa[4][3];
#pragma unroll
    for (int i = 0; i < 4; i++)
#pragma unroll
        for (int j = 0; j < 3; j++) sa[i][j] = 0.f;

#pragma unroll
    for (int ch = 0; ch < 2; ch++) {
        if (ch) __syncthreads();
        load_tile(ch * DC);
        __syncthreads();

        const float* q0 = tile + (WIN + 4 * ty) * TP2;
        const float* k0 = tile + tx * TP2;
#pragma unroll 2
        for (int d = 0; d < DC; d += 4) {
            float4 q[4], k[3];
#pragma unroll
            for (int ii = 0; ii < 4; ii++)
                q[ii] = *reinterpret_cast<const float4*>(q0 + ii * TP2 + d);
#pragma unroll
            for (int jj = 0; jj < 3; jj++)
                k[jj] = *reinterpret_cast<const float4*>(k0 + jj * 32 * TP2 + d);
#pragma unroll
            for (int ii = 0; ii < 4; ii++)
#pragma unroll
                for (int jj = 0; jj < 3; jj++) {
                    sa[ii][jj] = fmaf(q[ii].x, k[jj].x, sa[ii][jj]);
                    sa[ii][jj] = fmaf(q[ii].y, k[jj].y, sa[ii][jj]);
                    sa[ii][jj] = fmaf(q[ii].z, k[jj].z, sa[ii][jj]);
                    sa[ii][jj] = fmaf(q[ii].w, k[jj].w, sa[ii][jj]);
                }
        }
    }
#pragma unroll
    for (int ii = 0; ii < 4; ii++)
#pragma unroll
        for (int jj = 0; jj < 3; jj++)
            S[(4 * ty + ii) * SP + tx + 32 * jj] = sa[ii][jj];
    __syncthreads();

    // ---- phase 2: band softmax in-place -> dense alpha (zeros outside band) ----
    {
        const int i = tid >> 3;
        const int g = tid & 7;
        float* srow = S + i * SP;
        float m = -1e30f;
        float vals[8];
#pragma unroll
        for (int w8 = 0; w8 < 8; w8++) {
            vals[w8] = srow[i + g + 8 * w8];   // j = i + w, w in [0,64)
            m = fmaxf(m, vals[w8]);
        }
        m = fmaxf(m, __shfl_xor_sync(0xffffffffu, m, 1));
        m = fmaxf(m, __shfl_xor_sync(0xffffffffu, m, 2));
        m = fmaxf(m, __shfl_xor_sync(0xffffffffu, m, 4));
        float s = 0.f;
#pragma unroll
        for (int w8 = 0; w8 < 8; w8++) s += __expf(vals[w8] - m);
        s += __shfl_xor_sync(0xffffffffu, s, 1);
        s += __shfl_xor_sync(0xffffffffu, s, 2);
        s += __shfl_xor_sync(0xffffffffu, s, 4);
        const float inv = 1.f / s;
        __syncwarp();
#pragma unroll
        for (int jj = 0; jj < 12; jj++) {
            const int j = g * 12 + jj;
            float v = 0.f;
            if (j >= i && j < i + WIN) v = __expf(srow[j] - m) * inv;
            srow[j] = v;
        }
    }

    // ---- phase 3: chunk 1 first (resident), then chunk 0 ----
    const float* arow = S + 4 * ty * SP;
#pragma unroll
    for (int pass = 0; pass < 2; pass++) {
        const int ch = 1 - pass;
        __syncthreads();             // pass0: S visibility; pass1: done reading tile
        if (pass == 1) {
            load_tile(0);
            __syncthreads();
        }

        float cacc[4][8];
#pragma unroll
        for (int i = 0; i < 4; i++)
#pragma unroll
            for (int d = 0; d < 8; d++) cacc[i][d] = 0.f;

        for (int j = 0; j < 68; j++) {
            const int jj = 4 * ty + j;
            float a[4];
#pragma unroll
            for (int ii = 0; ii < 4; ii++) a[ii] = arow[ii * SP + jj];
            const float* kr = tile + jj * TP2 + 4 * tx;
#pragma unroll
            for (int q = 0; q < 2; q++) {
                float4 kv = *reinterpret_cast<const float4*>(kr + 128 * q);
#pragma unroll
                for (int ii = 0; ii < 4; ii++) {
                    cacc[ii][4 * q + 0] = fmaf(a[ii], kv.x, cacc[ii][4 * q + 0]);
                    cacc[ii][4 * q + 1] = fmaf(a[ii], kv.y, cacc[ii][4 * q + 1]);
                    cacc[ii][4 * q + 2] = fmaf(a[ii], kv.z, cacc[ii][4 * q + 2]);
                    cacc[ii][4 * q + 3] = fmaf(a[ii], kv.w, cacc[ii][4 * q + 3]);
                }
            }
        }
#pragma unroll
        for (int ii = 0; ii < 4; ii++) {
            float* crow = g_c + ((size_t)b * SEQ + qs + 4 * ty + ii) * DIM
                        + ch * DC + 4 * tx;
#pragma unroll
            for (int q = 0; q < 2; q++) {
                float4 v = make_float4(cacc[ii][4 * q], cacc[ii][4 * q + 1],
                                       cacc[ii][4 * q + 2], cacc[ii][4 * q + 3]);
                *reinterpret_cast<float4*>(crow + 128 * q) = v;
            }
        }
    }
}

// ---------------------------------------------------------------------------
// Output head (R9, 67.9us): out = sigmoid([c | x] @ Wc), mma.sync tf32.
// CTA 128x128, 256 threads, warp tile 64x32, 3-stage cp.async.16.
// A-frags via ldmatrix.x4; B K-major pitch 136, conflict-free LDS.32 frags.
// ---------------------------------------------------------------------------
__device__ __forceinline__ void mma_tf32(float* c, uint32_t a0, uint32_t a1,
                                         uint32_t a2, uint32_t a3,
                                         uint32_t b0, uint32_t b1) {
    asm volatile(
        "mma.sync.aligned.m16n8k8.row.col.f32.tf32.tf32.f32 "
        "{%0,%1,%2,%3}, {%4,%5,%6,%7}, {%8,%9}, {%0,%1,%2,%3};"
        : "+f"(c[0]), "+f"(c[1]), "+f"(c[2]), "+f"(c[3])
        : "r"(a0), "r"(a1), "r"(a2), "r"(a3), "r"(b0), "r"(b1));
}

__device__ __forceinline__ void issue_chunk(int c, int bm, int bn, int tid,
                                            const float* __restrict__ x,
                                            const float* __restrict__ Wc) {
    float* Ad = sm_dyn + (c % NSTAGE) * STF;
    float* Bd = Ad + AFL;
    const float* Asrc = (c < 16) ? g_c : x;
    const int koff = (c < 16) ? c * KC : c * KC - 512;
#pragma unroll
    for (int p = 0; p < 4; p++) {
        const int idx = tid + 256 * p;
        const int r   = idx >> 3;
        const int seg = (idx & 7) * 4;
        cpa16(smem_u32(Ad + r * APADW + seg),
              Asrc + (size_t)(bm + r) * DIM + koff + seg);
    }
#pragma unroll
    for (int p = 0; p < 4; p++) {
        const int idx = tid + 256 * p;
        const int k   = idx >> 5;
        const int n4  = (idx & 31) * 4;
        cpa16(smem_u32(Bd + k * BPADW + n4),
              Wc + (size_t)(c * KC + k) * DIM + bn + n4);
    }
    asm volatile("cp.async.commit_group;" ::: "memory");
}

__global__ __launch_bounds__(256, 2) void gemm_mma(const float* __restrict__ x,
                                                   const float* __restrict__ Wc,
                                                   float* __restrict__ out) {
    const int tid  = threadIdx.x;
    const int wid  = tid >> 5;
    const int lane = tid & 31;
    const int gid  = lane >> 2;
    const int tig  = lane & 3;
    const int wm   = wid & 1;
    const int wn   = wid >> 1;
    const int bm   = blockIdx.y * GM;
    const int bn   = blockIdx.x * GN;

    float acc[4][4][4];
#pragma unroll
    for (int i = 0; i < 4; i++)
#pragma unroll
        for (int j = 0; j < 4; j++)
#pragma unroll
            for (int k = 0; k < 4; k++) acc[i][j][k] = 0.f;

    const uint32_t sm_base = smem_u32(sm_dyn);
    // A ldmatrix: row = wm*64 + ma*16 + (lane&15), col = kk + ((lane>=16)?4:0)
    const uint32_t a_lm_off =
        (uint32_t)(((wm * 64 + (lane & 15)) * APADW + ((lane >> 4) << 2)) * 4);

    issue_chunk(0, bm, bn, tid, x, Wc);
    issue_chunk(1, bm, bn, tid, x, Wc);

    for (int c = 0; c < NCHUNK; c++) {
        if (c == NCHUNK - 1)
            asm volatile("cp.async.wait_group 0;" ::: "memory");
        else
            asm volatile("cp.async.wait_group 1;" ::: "memory");
        __syncthreads();
        if (c + 2 < NCHUNK) issue_chunk(c + 2, bm, bn, tid, x, Wc);

        const uint32_t As_addr = sm_base + (uint32_t)((c % NSTAGE) * STF * 4);
        const uint32_t* Bsu = reinterpret_cast<const uint32_t*>(
            sm_dyn + (c % NSTAGE) * STF + AFL);
#pragma unroll
        for (int kk = 0; kk < KC; kk += 8) {
            uint32_t a[4][4], bfr[4][2];
#pragma unroll
            for (int ma = 0; ma < 4; ma++)
                ldsm_x4(a[ma][0], a[ma][1], a[ma][2], a[ma][3],
                        As_addr + a_lm_off + (uint32_t)((ma * 16 * APADW + kk) * 4));
#pragma unroll
            for (int na = 0; na < 4; na++) {
                const int n = wn * 32 + na * 8 + gid;
                bfr[na][0] = Bsu[(kk + tig) * BPADW + n];
                bfr[na][1] = Bsu[(kk + tig + 4) * BPADW + n];
            }
#pragma unroll
            for (int ma = 0; ma < 4; ma++)
#pragma unroll
                for (int na = 0; na < 4; na++)
                    mma_tf32(acc[ma][na], a[ma][0], a[ma][1], a[ma][2], a[ma][3],
                             bfr[na][0], bfr[na][1]);
        }
    }

    // ---- epilogue: sigmoid + store ----
#pragma unroll
    for (int ma = 0; ma < 4; ma++) {
#pragma unroll
        for (int na = 0; na < 4; na++) {
            const int row = bm + wm * 64 + ma * 16 + gid;
            const int col = bn + wn * 32 + na * 8 + 2 * tig;
            float2 v0, v1;
            v0.x = 1.f / (1.f + __expf(-acc[ma][na][0]));
            v0.y = 1.f / (1.f + __expf(-acc[ma][na][1]));
            v1.x = 1.f / (1.f + __expf(-acc[ma][na][2]));
            v1.y = 1.f / (1.f + __expf(-acc[ma][na][3]));
            *reinterpret_cast<float2*>(out + (size_t)row * DIM + col) = v0;
            *reinterpret_cast<float2*>(out + (size_t)(row + 8) * DIM + col) = v1;
        }
    }
}

extern "C" void kernel_launch(void* const* d_in, const int* in_sizes, int n_in,
                              void* d_out, int out_size) {
    const float* x  = (const float*)d_in[0];   // (4, 2048, 512) fp32
    const float* Wc = (const float*)d_in[1];   // (1024, 512) fp32
    float* out = (float*)d_out;                // (4, 2048, 512) fp32

    const size_t attn_smem = (size_t)(SROWS * TP2 + QT * SP) * sizeof(float); // 112,640 B
    cudaFuncSetAttribute(attn_kernel, cudaFuncAttributeMaxDynamicSharedMemorySize,
                         (int)attn_smem);
    attn_kernel<<<BATCH * (SEQ / QT), 256, attn_smem>>>(x);

    const size_t gemm_smem = (size_t)(NSTAGE * STF) * sizeof(float);  // 107,520 B
    cudaFuncSetAttribute(gemm_mma, cudaFuncAttributeMaxDynamicSharedMemorySize,
                         (int)gemm_smem);
    dim3 grid(DIM / GN, (BATCH * SEQ) / GM);   // (4, 64)
    gemm_mma<<<grid, 256, gemm_smem>>>(x, Wc, out);
}

// round 14
// speedup vs baseline: 1.4181x; 1.2219x over previous
#include <cuda_runtime.h>
#include <cuda_fp16.h>
#include <cstdint>
#include <math.h>

// ---------------- problem constants ----------------
#define BATCH 4
#define SEQ   2048
#define DIM   512
#define WIN   64
#define QT    32

// attention smem layout (D processed in 2 chunks of 256)
#define DC    256
#define TP2   260             // tile row pitch (floats)
#define SROWS 96
#define SP    100             // score row pitch

// gemm tiling (mma.sync fp16 m16n8k16), fused K=1024
#define GM 128
#define GN 128
#define KC 32
#define NCHUNK (1024 / KC)    // 32
#define APH 40                // A smem pitch in halves (80 B rows; banks 20r mod 32 distinct)
#define BPH 40                // B smem pitch in halves (n-major)
#define AFLH (GM * APH)       // 5120 halves
#define BFLH (GN * BPH)       // 5120 halves
#define STFH (AFLH + BFLH)    // 10240 halves = 20480 B per stage
#define NSTAGE 4

// device scratch (no cudaMalloc allowed)
__device__ __half g_hc[BATCH * SEQ * DIM];         // context, fp16
__device__ __half g_hx[BATCH * SEQ * DIM];         // x, fp16 (written by attention)
__device__ __half g_hwt[DIM * 1024];               // Wc transposed: [n][k] fp16

__device__ __forceinline__ uint32_t smem_u32(const void* p) {
    uint32_t a;
    asm("{ .reg .u64 t; cvta.to.shared.u64 t, %1; cvt.u32.u64 %0, t; }"
        : "=r"(a) : "l"(p));
    return a;
}
__device__ __forceinline__ void cpa16(uint32_t d, const void* s) {
    asm volatile("cp.async.cg.shared.global [%0], [%1], 16;" :: "r"(d), "l"(s));
}
__device__ __forceinline__ void ldsm_x4(uint32_t& r0, uint32_t& r1,
                                        uint32_t& r2, uint32_t& r3, uint32_t addr) {
    asm volatile("ldmatrix.sync.aligned.m8n8.x4.shared.b16 {%0,%1,%2,%3}, [%4];"
                 : "=r"(r0), "=r"(r1), "=r"(r2), "=r"(r3) : "r"(addr));
}

extern __shared__ float sm_dyn[];

// ---------------------------------------------------------------------------
// Wc convert+transpose: g_hwt[n][k] = fp16(Wc[k][n]). 2048 blocks x 256.
// ---------------------------------------------------------------------------
__global__ void convw_kernel(const float* __restrict__ Wc) {
    const int idx = blockIdx.x * 256 + threadIdx.x;   // 524288 total
    const int n = idx >> 10;
    const int k = idx & 1023;
    g_hwt[n * 1024 + k] = __float2half_rn(Wc[(size_t)k * DIM + n]);
}

// ---------------------------------------------------------------------------
// Attention: 256 CTAs, 256 threads, QT=32 queries, 2 CTAs/SM.
// Dense phase 1 (also converts this CTA's 32 query rows to g_hx, free);
// phase 3 chunk 1 first (resident), writes g_hc as fp16.
// ---------------------------------------------------------------------------
__global__ __launch_bounds__(256, 2) void attn_kernel(const float* __restrict__ x) {
    float* tile = sm_dyn;                 // [96][TP2]
    float* S    = sm_dyn + SROWS * TP2;   // [32][SP]

    const int tid = threadIdx.x;
    const int b   = blockIdx.x >> 6;
    const int qs  = (blockIdx.x & 63) * QT;
    const float* xb = x + (size_t)b * SEQ * DIM;

    const int ty = tid >> 5;
    const int tx = tid & 31;

    auto load_tile = [&](int d0) {
#pragma unroll 8
        for (int p = 0; p < 24; p++) {
            const int idx = tid + 256 * p;
            const int r   = idx >> 6;
            const int c4  = (idx & 63) << 2;
            const int gr  = qs - WIN + r;
            float4 v = make_float4(0.f, 0.f, 0.f, 0.f);
            if (gr >= 0)
                v = *reinterpret_cast<const float4*>(xb + (size_t)gr * DIM + d0 + c4);
            *reinterpret_cast<float4*>(tile + r * TP2 + c4) = v;
        }
    };

    // ---- phase 1 (+ hx conversion of query rows) ----
    float sa[4][3];
#pragma unroll
    for (int i = 0; i < 4; i++)
#pragma unroll
        for (int j = 0; j < 3; j++) sa[i][j] = 0.f;

#pragma unroll
    for (int ch = 0; ch < 2; ch++) {
        if (ch) __syncthreads();
        load_tile(ch * DC);
        __syncthreads();

        // convert tile rows 64..95 (this CTA's query rows) -> g_hx
#pragma unroll
        for (int p = 0; p < 8; p++) {
            const int idx = tid + 256 * p;       // 2048 float4
            const int r   = idx >> 6;            // 0..31
            const int c4  = (idx & 63) << 2;
            float4 v = *reinterpret_cast<const float4*>(tile + (WIN + r) * TP2 + c4);
            __half2 h0 = __floats2half2_rn(v.x, v.y);
            __half2 h1 = __floats2half2_rn(v.z, v.w);
            uint2 uu;
            uu.x = *reinterpret_cast<uint32_t*>(&h0);
            uu.y = *reinterpret_cast<uint32_t*>(&h1);
            *reinterpret_cast<uint2*>(
                g_hx + ((size_t)(b * SEQ + qs + r) * DIM + ch * DC + c4)) = uu;
        }

        const float* q0 = tile + (WIN + 4 * ty) * TP2;
        const float* k0 = tile + tx * TP2;
#pragma unroll 2
        for (int d = 0; d < DC; d += 4) {
            float4 q[4], k[3];
#pragma unroll
            for (int ii = 0; ii < 4; ii++)
                q[ii] = *reinterpret_cast<const float4*>(q0 + ii * TP2 + d);
#pragma unroll
            for (int jj = 0; jj < 3; jj++)
                k[jj] = *reinterpret_cast<const float4*>(k0 + jj * 32 * TP2 + d);
#pragma unroll
            for (int ii = 0; ii < 4; ii++)
#pragma unroll
                for (int jj = 0; jj < 3; jj++) {
                    sa[ii][jj] = fmaf(q[ii].x, k[jj].x, sa[ii][jj]);
                    sa[ii][jj] = fmaf(q[ii].y, k[jj].y, sa[ii][jj]);
                    sa[ii][jj] = fmaf(q[ii].z, k[jj].z, sa[ii][jj]);
                    sa[ii][jj] = fmaf(q[ii].w, k[jj].w, sa[ii][jj]);
                }
        }
    }
#pragma unroll
    for (int ii = 0; ii < 4; ii++)
#pragma unroll
        for (int jj = 0; jj < 3; jj++)
            S[(4 * ty + ii) * SP + tx + 32 * jj] = sa[ii][jj];
    __syncthreads();

    // ---- phase 2: band softmax -> dense alpha ----
    {
        const int i = tid >> 3;
        const int g = tid & 7;
        float* srow = S + i * SP;
        float m = -1e30f;
        float vals[8];
#pragma unroll
        for (int w8 = 0; w8 < 8; w8++) {
            vals[w8] = srow[i + g + 8 * w8];
            m = fmaxf(m, vals[w8]);
        }
        m = fmaxf(m, __shfl_xor_sync(0xffffffffu, m, 1));
        m = fmaxf(m, __shfl_xor_sync(0xffffffffu, m, 2));
        m = fmaxf(m, __shfl_xor_sync(0xffffffffu, m, 4));
        float s = 0.f;
#pragma unroll
        for (int w8 = 0; w8 < 8; w8++) s += __expf(vals[w8] - m);
        s += __shfl_xor_sync(0xffffffffu, s, 1);
        s += __shfl_xor_sync(0xffffffffu, s, 2);
        s += __shfl_xor_sync(0xffffffffu, s, 4);
        const float inv = 1.f / s;
        __syncwarp();
#pragma unroll
        for (int jj = 0; jj < 12; jj++) {
            const int j = g * 12 + jj;
            float v = 0.f;
            if (j >= i && j < i + WIN) v = __expf(srow[j] - m) * inv;
            srow[j] = v;
        }
    }

    // ---- phase 3: chunk 1 first (resident), then chunk 0; write fp16 ----
    const float* arow = S + 4 * ty * SP;
#pragma unroll
    for (int pass = 0; pass < 2; pass++) {
        const int ch = 1 - pass;
        __syncthreads();
        if (pass == 1) {
            load_tile(0);
            __syncthreads();
        }

        float cacc[4][8];
#pragma unroll
        for (int i = 0; i < 4; i++)
#pragma unroll
            for (int d = 0; d < 8; d++) cacc[i][d] = 0.f;

        for (int j = 0; j < 68; j++) {
            const int jj = 4 * ty + j;
            float a[4];
#pragma unroll
            for (int ii = 0; ii < 4; ii++) a[ii] = arow[ii * SP + jj];
            const float* kr = tile + jj * TP2 + 4 * tx;
#pragma unroll
            for (int q = 0; q < 2; q++) {
                float4 kv = *reinterpret_cast<const float4*>(kr + 128 * q);
#pragma unroll
                for (int ii = 0; ii < 4; ii++) {
                    cacc[ii][4 * q + 0] = fmaf(a[ii], kv.x, cacc[ii][4 * q + 0]);
                    cacc[ii][4 * q + 1] = fmaf(a[ii], kv.y, cacc[ii][4 * q + 1]);
                    cacc[ii][4 * q + 2] = fmaf(a[ii], kv.z, cacc[ii][4 * q + 2]);
                    cacc[ii][4 * q + 3] = fmaf(a[ii], kv.w, cacc[ii][4 * q + 3]);
                }
            }
        }
#pragma unroll
        for (int ii = 0; ii < 4; ii++) {
            __half* crow = g_hc + ((size_t)(b * SEQ + qs + 4 * ty + ii)) * DIM
                         + ch * DC + 4 * tx;
#pragma unroll
            for (int q = 0; q < 2; q++) {
                __half2 h0 = __floats2half2_rn(cacc[ii][4 * q + 0], cacc[ii][4 * q + 1]);
                __half2 h1 = __floats2half2_rn(cacc[ii][4 * q + 2], cacc[ii][4 * q + 3]);
                uint2 uu;
                uu.x = *reinterpret_cast<uint32_t*>(&h0);
                uu.y = *reinterpret_cast<uint32_t*>(&h1);
                *reinterpret_cast<uint2*>(crow + 128 * q) = uu;
            }
        }
    }
}

// ---------------------------------------------------------------------------
// Output head: out = sigmoid([c | x] @ Wc), fp16 mma m16n8k16 (fp32 accum).
// CTA 128x128, 256 threads, warp tile 64x32, 4-stage cp.async.
// A [m][k] pitch 40 halves, B [n][k] pitch 40 halves; all frags ldmatrix.x4.
// ---------------------------------------------------------------------------
__device__ __forceinline__ void mma_f16(float* c, uint32_t a0, uint32_t a1,
                                        uint32_t a2, uint32_t a3,
                                        uint32_t b0, uint32_t b1) {
    asm volatile(
        "mma.sync.aligned.m16n8k16.row.col.f32.f16.f16.f32 "
        "{%0,%1,%2,%3}, {%4,%5,%6,%7}, {%8,%9}, {%0,%1,%2,%3};"
        : "+f"(c[0]), "+f"(c[1]), "+f"(c[2]), "+f"(c[3])
        : "r"(a0), "r"(a1), "r"(a2), "r"(a3), "r"(b0), "r"(b1));
}

__device__ __forceinline__ void issue_chunk(int c, int bm, int bn, int tid) {
    __half* Ad = reinterpret_cast<__half*>(sm_dyn) + (c & 3) * STFH;
    __half* Bd = Ad + AFLH;
    const __half* Asrc = (c < 16) ? g_hc : g_hx;
    const int koff = (c < 16) ? c * KC : c * KC - 512;
    // A: 128 rows x 32 halves (64 B) = 512 x 16B
#pragma unroll
    for (int p = 0; p < 2; p++) {
        const int idx = tid + 256 * p;
        const int r   = idx >> 2;
        const int seg = idx & 3;
        cpa16(smem_u32(Ad + r * APH + seg * 8),
              Asrc + (size_t)(bm + r) * DIM + koff + seg * 8);
    }
    // B: 128 n-rows x 32 halves from g_hwt[n][k]
#pragma unroll
    for (int p = 0; p < 2; p++) {
        const int idx = tid + 256 * p;
        const int n   = idx >> 2;
        const int seg = idx & 3;
        cpa16(smem_u32(Bd + n * BPH + seg * 8),
              g_hwt + (size_t)(bn + n) * 1024 + c * KC + seg * 8);
    }
    asm volatile("cp.async.commit_group;" ::: "memory");
}

__global__ __launch_bounds__(256, 2) void gemm_mma(float* __restrict__ out) {
    const int tid  = threadIdx.x;
    const int wid  = tid >> 5;
    const int lane = tid & 31;
    const int gid  = lane >> 2;
    const int tig  = lane & 3;
    const int wm   = wid & 1;
    const int wn   = wid >> 1;
    const int bm   = blockIdx.y * GM;
    const int bn   = blockIdx.x * GN;

    float acc[4][4][4];
#pragma unroll
    for (int i = 0; i < 4; i++)
#pragma unroll
        for (int j = 0; j < 4; j++)
#pragma unroll
            for (int k = 0; k < 4; k++) acc[i][j][k] = 0.f;

    const uint32_t sm_base = smem_u32(sm_dyn);
    // A ldmatrix lane offset: row = wm*64 + (lane&15), col-group = (lane>>4)*8
    const uint32_t a_off =
        (uint32_t)(((wm * 64 + (lane & 15)) * APH + ((lane >> 4) & 1) * 8) * 2);
    // B ldmatrix lane offset: row = wn*32 + (lane&7) + ((lane>>4)&1)*8,
    // col-group = ((lane>>3)&1)*8
    const uint32_t b_off =
        (uint32_t)(((wn * 32 + (lane & 7) + ((lane >> 4) & 1) * 8) * BPH
                    + ((lane >> 3) & 1) * 8) * 2);

    issue_chunk(0, bm, bn, tid);
    issue_chunk(1, bm, bn, tid);
    issue_chunk(2, bm, bn, tid);

    for (int c = 0; c < NCHUNK; c++) {
        if (c <= NCHUNK - 3)
            asm volatile("cp.async.wait_group 2;" ::: "memory");
        else if (c == NCHUNK - 2)
            asm volatile("cp.async.wait_group 1;" ::: "memory");
        else
            asm volatile("cp.async.wait_group 0;" ::: "memory");
        __syncthreads();
        if (c + 3 < NCHUNK) issue_chunk(c + 3, bm, bn, tid);

        const uint32_t As_addr = sm_base + (uint32_t)((c & 3) * STFH * 2);
        const uint32_t Bs_addr = As_addr + (uint32_t)(AFLH * 2);
#pragma unroll
        for (int kk = 0; kk < KC; kk += 16) {
            uint32_t a[4][4], bb[2][4];
#pragma unroll
            for (int ma = 0; ma < 4; ma++)
                ldsm_x4(a[ma][0], a[ma][1], a[ma][2], a[ma][3],
                        As_addr + a_off + (uint32_t)((ma * 16 * APH + kk) * 2));
#pragma unroll
            for (int p = 0; p < 2; p++)
                ldsm_x4(bb[p][0], bb[p][1], bb[p][2], bb[p][3],
                        Bs_addr + b_off + (uint32_t)((p * 16 * BPH + kk) * 2));
#pragma unroll
            for (int ma = 0; ma < 4; ma++)
#pragma unroll
                for (int na = 0; na < 4; na++)
                    mma_f16(acc[ma][na], a[ma][0], a[ma][1], a[ma][2], a[ma][3],
                            bb[na >> 1][(na & 1) * 2], bb[na >> 1][(na & 1) * 2 + 1]);
        }
    }

    // ---- epilogue: sigmoid + store ----
#pragma unroll
    for (int ma = 0; ma < 4; ma++) {
#pragma unroll
        for (int na = 0; na < 4; na++) {
            const int row = bm + wm * 64 + ma * 16 + gid;
            const int col = bn + wn * 32 + na * 8 + 2 * tig;
            float2 v0, v1;
            v0.x = 1.f / (1.f + __expf(-acc[ma][na][0]));
            v0.y = 1.f / (1.f + __expf(-acc[ma][na][1]));
            v1.x = 1.f / (1.f + __expf(-acc[ma][na][2]));
            v1.y = 1.f / (1.f + __expf(-acc[ma][na][3]));
            *reinterpret_cast<float2*>(out + (size_t)row * DIM + col) = v0;
            *reinterpret_cast<float2*>(out + (size_t)(row + 8) * DIM + col) = v1;
        }
    }
}

extern "C" void kernel_launch(void* const* d_in, const int* in_sizes, int n_in,
                              void* d_out, int out_size) {
    const float* x  = (const float*)d_in[0];   // (4, 2048, 512) fp32
    const float* Wc = (const float*)d_in[1];   // (1024, 512) fp32
    float* out = (float*)d_out;                // (4, 2048, 512) fp32

    convw_kernel<<<2048, 256>>>(Wc);

    const size_t attn_smem = (size_t)(SROWS * TP2 + QT * SP) * sizeof(float); // 112,640 B
    cudaFuncSetAttribute(attn_kernel, cudaFuncAttributeMaxDynamicSharedMemorySize,
                         (int)attn_smem);
    attn_kernel<<<BATCH * (SEQ / QT), 256, attn_smem>>>(x);

    const size_t gemm_smem = (size_t)(NSTAGE * STFH) * sizeof(__half);  // 81,920 B
    cudaFuncSetAttribute(gemm_mma, cudaFuncAttributeMaxDynamicSharedMemorySize,
                         (int)gemm_smem);
    dim3 grid(DIM / GN, (BATCH * SEQ) / GM);   // (4, 64)
    gemm_mma<<<grid, 256, gemm_smem>>>(out);
}

// round 15
// speedup vs baseline: 1.4275x; 1.0066x over previous
#include <cuda_runtime.h>
#include <cuda_fp16.h>
#include <cstdint>
#include <math.h>

// ---------------- problem constants ----------------
#define BATCH 4
#define SEQ   2048
#define DIM   512
#define WIN   64
#define QT    32

// attention smem layout (D processed in 2 chunks of 256)
#define DC    256
#define TP2   260             // tile row pitch (floats)
#define SROWS 96
#define SP    100             // score row pitch

// gemm tiling (mma.sync fp16 m16n8k16), fused K=1024
#define GM 128
#define GN 128
#define KC 32
#define NCHUNK (1024 / KC)    // 32
#define APH 40                // A smem pitch in halves (80 B rows; banks 20r mod 32 distinct)
#define BPH 40                // B smem pitch in halves (n-major)
#define AFLH (GM * APH)       // 5120 halves
#define BFLH (GN * BPH)       // 5120 halves
#define STFH (AFLH + BFLH)    // 10240 halves = 20480 B per stage
#define NSTAGE 4

// device scratch (no cudaMalloc allowed)
__device__ __half g_hc[BATCH * SEQ * DIM];         // context, fp16
__device__ __half g_hx[BATCH * SEQ * DIM];         // x, fp16 (written by attention)
__device__ __half g_hwt[DIM * 1024];               // Wc transposed: [n][k] fp16

__device__ __forceinline__ uint32_t smem_u32(const void* p) {
    uint32_t a;
    asm("{ .reg .u64 t; cvta.to.shared.u64 t, %1; cvt.u32.u64 %0, t; }"
        : "=r"(a) : "l"(p));
    return a;
}
__device__ __forceinline__ void cpa16(uint32_t d, const void* s) {
    asm volatile("cp.async.cg.shared.global [%0], [%1], 16;" :: "r"(d), "l"(s));
}
__device__ __forceinline__ void ldsm_x4(uint32_t& r0, uint32_t& r1,
                                        uint32_t& r2, uint32_t& r3, uint32_t addr) {
    asm volatile("ldmatrix.sync.aligned.m8n8.x4.shared.b16 {%0,%1,%2,%3}, [%4];"
                 : "=r"(r0), "=r"(r1), "=r"(r2), "=r"(r3) : "r"(addr));
}

extern __shared__ float sm_dyn[];

// ---------------------------------------------------------------------------
// Wc convert+transpose, tiled: g_hwt[n][k] = fp16(Wc[k][n]).
// 32x32 tiles, coalesced reads AND writes, 33-pitch smem (no conflicts).
// grid 512 (16 n-tiles x 32 k-tiles), block 256.
// ---------------------------------------------------------------------------
__global__ __launch_bounds__(256) void convw_kernel(const float* __restrict__ Wc) {
    __shared__ float t[32][33];
    const int tx = threadIdx.x & 31;
    const int ty = threadIdx.x >> 5;          // 0..7
    const int n0 = (blockIdx.x & 15) * 32;
    const int k0 = (blockIdx.x >> 4) * 32;
#pragma unroll
    for (int i = 0; i < 4; i++)
        t[ty + 8 * i][tx] = Wc[(size_t)(k0 + ty + 8 * i) * DIM + n0 + tx];
    __syncthreads();
#pragma unroll
    for (int i = 0; i < 4; i++)
        g_hwt[(size_t)(n0 + ty + 8 * i) * 1024 + k0 + tx] =
            __float2half_rn(t[tx][ty + 8 * i]);
}

// ---------------------------------------------------------------------------
// Attention: 256 CTAs, 256 threads, QT=32 queries, 2 CTAs/SM. (R14, measured)
// ---------------------------------------------------------------------------
__global__ __launch_bounds__(256, 2) void attn_kernel(const float* __restrict__ x) {
    float* tile = sm_dyn;                 // [96][TP2]
    float* S    = sm_dyn + SROWS * TP2;   // [32][SP]

    const int tid = threadIdx.x;
    const int b   = blockIdx.x >> 6;
    const int qs  = (blockIdx.x & 63) * QT;
    const float* xb = x + (size_t)b * SEQ * DIM;

    const int ty = tid >> 5;
    const int tx = tid & 31;

    auto load_tile = [&](int d0) {
#pragma unroll 8
        for (int p = 0; p < 24; p++) {
            const int idx = tid + 256 * p;
            const int r   = idx >> 6;
            const int c4  = (idx & 63) << 2;
            const int gr  = qs - WIN + r;
            float4 v = make_float4(0.f, 0.f, 0.f, 0.f);
            if (gr >= 0)
                v = *reinterpret_cast<const float4*>(xb + (size_t)gr * DIM + d0 + c4);
            *reinterpret_cast<float4*>(tile + r * TP2 + c4) = v;
        }
    };

    // ---- phase 1 (+ hx conversion of query rows) ----
    float sa[4][3];
#pragma unroll
    for (int i = 0; i < 4; i++)
#pragma unroll
        for (int j = 0; j < 3; j++) sa[i][j] = 0.f;

#pragma unroll
    for (int ch = 0; ch < 2; ch++) {
        if (ch) __syncthreads();
        load_tile(ch * DC);
        __syncthreads();

        // convert tile rows 64..95 (this CTA's query rows) -> g_hx
#pragma unroll
        for (int p = 0; p < 8; p++) {
            const int idx = tid + 256 * p;       // 2048 float4
            const int r   = idx >> 6;            // 0..31
            const int c4  = (idx & 63) << 2;
            float4 v = *reinterpret_cast<const float4*>(tile + (WIN + r) * TP2 + c4);
            __half2 h0 = __floats2half2_rn(v.x, v.y);
            __half2 h1 = __floats2half2_rn(v.z, v.w);
            uint2 uu;
            uu.x = *reinterpret_cast<uint32_t*>(&h0);
            uu.y = *reinterpret_cast<uint32_t*>(&h1);
            *reinterpret_cast<uint2*>(
                g_hx + ((size_t)(b * SEQ + qs + r) * DIM + ch * DC + c4)) = uu;
        }

        const float* q0 = tile + (WIN + 4 * ty) * TP2;
        const float* k0 = tile + tx * TP2;
#pragma unroll 2
        for (int d = 0; d < DC; d += 4) {
            float4 q[4], k[3];
#pragma unroll
            for (int ii = 0; ii < 4; ii++)
                q[ii] = *reinterpret_cast<const float4*>(q0 + ii * TP2 + d);
#pragma unroll
            for (int jj = 0; jj < 3; jj++)
                k[jj] = *reinterpret_cast<const float4*>(k0 + jj * 32 * TP2 + d);
#pragma unroll
            for (int ii = 0; ii < 4; ii++)
#pragma unroll
                for (int jj = 0; jj < 3; jj++) {
                    sa[ii][jj] = fmaf(q[ii].x, k[jj].x, sa[ii][jj]);
                    sa[ii][jj] = fmaf(q[ii].y, k[jj].y, sa[ii][jj]);
                    sa[ii][jj] = fmaf(q[ii].z, k[jj].z, sa[ii][jj]);
                    sa[ii][jj] = fmaf(q[ii].w, k[jj].w, sa[ii][jj]);
                }
        }
    }
#pragma unroll
    for (int ii = 0; ii < 4; ii++)
#pragma unroll
        for (int jj = 0; jj < 3; jj++)
            S[(4 * ty + ii) * SP + tx + 32 * jj] = sa[ii][jj];
    __syncthreads();

    // ---- phase 2: band softmax -> dense alpha ----
    {
        const int i = tid >> 3;
        const int g = tid & 7;
        float* srow = S + i * SP;
        float m = -1e30f;
        float vals[8];
#pragma unroll
        for (int w8 = 0; w8 < 8; w8++) {
            vals[w8] = srow[i + g + 8 * w8];
            m = fmaxf(m, vals[w8]);
        }
        m = fmaxf(m, __shfl_xor_sync(0xffffffffu, m, 1));
        m = fmaxf(m, __shfl_xor_sync(0xffffffffu, m, 2));
        m = fmaxf(m, __shfl_xor_sync(0xffffffffu, m, 4));
        float s = 0.f;
#pragma unroll
        for (int w8 = 0; w8 < 8; w8++) s += __expf(vals[w8] - m);
        s += __shfl_xor_sync(0xffffffffu, s, 1);
        s += __shfl_xor_sync(0xffffffffu, s, 2);
        s += __shfl_xor_sync(0xffffffffu, s, 4);
        const float inv = 1.f / s;
        __syncwarp();
#pragma unroll
        for (int jj = 0; jj < 12; jj++) {
            const int j = g * 12 + jj;
            float v = 0.f;
            if (j >= i && j < i + WIN) v = __expf(srow[j] - m) * inv;
            srow[j] = v;
        }
    }

    // ---- phase 3: chunk 1 first (resident), then chunk 0; write fp16 ----
    const float* arow = S + 4 * ty * SP;
#pragma unroll
    for (int pass = 0; pass < 2; pass++) {
        const int ch = 1 - pass;
        __syncthreads();
        if (pass == 1) {
            load_tile(0);
            __syncthreads();
        }

        float cacc[4][8];
#pragma unroll
        for (int i = 0; i < 4; i++)
#pragma unroll
            for (int d = 0; d < 8; d++) cacc[i][d] = 0.f;

        for (int j = 0; j < 68; j++) {
            const int jj = 4 * ty + j;
            float a[4];
#pragma unroll
            for (int ii = 0; ii < 4; ii++) a[ii] = arow[ii * SP + jj];
            const float* kr = tile + jj * TP2 + 4 * tx;
#pragma unroll
            for (int q = 0; q < 2; q++) {
                float4 kv = *reinterpret_cast<const float4*>(kr + 128 * q);
#pragma unroll
                for (int ii = 0; ii < 4; ii++) {
                    cacc[ii][4 * q + 0] = fmaf(a[ii], kv.x, cacc[ii][4 * q + 0]);
                    cacc[ii][4 * q + 1] = fmaf(a[ii], kv.y, cacc[ii][4 * q + 1]);
                    cacc[ii][4 * q + 2] = fmaf(a[ii], kv.z, cacc[ii][4 * q + 2]);
                    cacc[ii][4 * q + 3] = fmaf(a[ii], kv.w, cacc[ii][4 * q + 3]);
                }
            }
        }
#pragma unroll
        for (int ii = 0; ii < 4; ii++) {
            __half* crow = g_hc + ((size_t)(b * SEQ + qs + 4 * ty + ii)) * DIM
                         + ch * DC + 4 * tx;
#pragma unroll
            for (int q = 0; q < 2; q++) {
                __half2 h0 = __floats2half2_rn(cacc[ii][4 * q + 0], cacc[ii][4 * q + 1]);
                __half2 h1 = __floats2half2_rn(cacc[ii][4 * q + 2], cacc[ii][4 * q + 3]);
                uint2 uu;
                uu.x = *reinterpret_cast<uint32_t*>(&h0);
                uu.y = *reinterpret_cast<uint32_t*>(&h1);
                *reinterpret_cast<uint2*>(crow + 128 * q) = uu;
            }
        }
    }
}

// ---------------------------------------------------------------------------
// Output head (R14, measured ~43us): out = sigmoid([c | x] @ Wc), fp16 mma.
// ---------------------------------------------------------------------------
__device__ __forceinline__ void mma_f16(float* c, uint32_t a0, uint32_t a1,
                                        uint32_t a2, uint32_t a3,
                                        uint32_t b0, uint32_t b1) {
    asm volatile(
        "mma.sync.aligned.m16n8k16.row.col.f32.f16.f16.f32 "
        "{%0,%1,%2,%3}, {%4,%5,%6,%7}, {%8,%9}, {%0,%1,%2,%3};"
        : "+f"(c[0]), "+f"(c[1]), "+f"(c[2]), "+f"(c[3])
        : "r"(a0), "r"(a1), "r"(a2), "r"(a3), "r"(b0), "r"(b1));
}

__device__ __forceinline__ void issue_chunk(int c, int bm, int bn, int tid) {
    __half* Ad = reinterpret_cast<__half*>(sm_dyn) + (c & 3) * STFH;
    __half* Bd = Ad + AFLH;
    const __half* Asrc = (c < 16) ? g_hc : g_hx;
    const int koff = (c < 16) ? c * KC : c * KC - 512;
#pragma unroll
    for (int p = 0; p < 2; p++) {
        const int idx = tid + 256 * p;
        const int r   = idx >> 2;
        const int seg = idx & 3;
        cpa16(smem_u32(Ad + r * APH + seg * 8),
              Asrc + (size_t)(bm + r) * DIM + koff + seg * 8);
    }
#pragma unroll
    for (int p = 0; p < 2; p++) {
        const int idx = tid + 256 * p;
        const int n   = idx >> 2;
        const int seg = idx & 3;
        cpa16(smem_u32(Bd + n * BPH + seg * 8),
              g_hwt + (size_t)(bn + n) * 1024 + c * KC + seg * 8);
    }
    asm volatile("cp.async.commit_group;" ::: "memory");
}

__global__ __launch_bounds__(256, 2) void gemm_mma(float* __restrict__ out) {
    const int tid  = threadIdx.x;
    const int wid  = tid >> 5;
    const int lane = tid & 31;
    const int gid  = lane >> 2;
    const int tig  = lane & 3;
    const int wm   = wid & 1;
    const int wn   = wid >> 1;
    const int bm   = blockIdx.y * GM;
    const int bn   = blockIdx.x * GN;

    float acc[4][4][4];
#pragma unroll
    for (int i = 0; i < 4; i++)
#pragma unroll
        for (int j = 0; j < 4; j++)
#pragma unroll
            for (int k = 0; k < 4; k++) acc[i][j][k] = 0.f;

    const uint32_t sm_base = smem_u32(sm_dyn);
    const uint32_t a_off =
        (uint32_t)(((wm * 64 + (lane & 15)) * APH + ((lane >> 4) & 1) * 8) * 2);
    const uint32_t b_off =
        (uint32_t)(((wn * 32 + (lane & 7) + ((lane >> 4) & 1) * 8) * BPH
                    + ((lane >> 3) & 1) * 8) * 2);

    issue_chunk(0, bm, bn, tid);
    issue_chunk(1, bm, bn, tid);
    issue_chunk(2, bm, bn, tid);

    for (int c = 0; c < NCHUNK; c++) {
        if (c <= NCHUNK - 3)
            asm volatile("cp.async.wait_group 2;" ::: "memory");
        else if (c == NCHUNK - 2)
            asm volatile("cp.async.wait_group 1;" ::: "memory");
        else
            asm volatile("cp.async.wait_group 0;" ::: "memory");
        __syncthreads();
        if (c + 3 < NCHUNK) issue_chunk(c + 3, bm, bn, tid);

        const uint32_t As_addr = sm_base + (uint32_t)((c & 3) * STFH * 2);
        const uint32_t Bs_addr = As_addr + (uint32_t)(AFLH * 2);
#pragma unroll
        for (int kk = 0; kk < KC; kk += 16) {
            uint32_t a[4][4], bb[2][4];
#pragma unroll
            for (int ma = 0; ma < 4; ma++)
                ldsm_x4(a[ma][0], a[ma][1], a[ma][2], a[ma][3],
                        As_addr + a_off + (uint32_t)((ma * 16 * APH + kk) * 2));
#pragma unroll
            for (int p = 0; p < 2; p++)
                ldsm_x4(bb[p][0], bb[p][1], bb[p][2], bb[p][3],
                        Bs_addr + b_off + (uint32_t)((p * 16 * BPH + kk) * 2));
#pragma unroll
            for (int ma = 0; ma < 4; ma++)
#pragma unroll
                for (int na = 0; na < 4; na++)
                    mma_f16(acc[ma][na], a[ma][0], a[ma][1], a[ma][2], a[ma][3],
                            bb[na >> 1][(na & 1) * 2], bb[na >> 1][(na & 1) * 2 + 1]);
        }
    }

    // ---- epilogue: sigmoid + store ----
#pragma unroll
    for (int ma = 0; ma < 4; ma++) {
#pragma unroll
        for (int na = 0; na < 4; na++) {
            const int row = bm + wm * 64 + ma * 16 + gid;
            const int col = bn + wn * 32 + na * 8 + 2 * tig;
            float2 v0, v1;
            v0.x = 1.f / (1.f + __expf(-acc[ma][na][0]));
            v0.y = 1.f / (1.f + __expf(-acc[ma][na][1]));
            v1.x = 1.f / (1.f + __expf(-acc[ma][na][2]));
            v1.y = 1.f / (1.f + __expf(-acc[ma][na][3]));
            *reinterpret_cast<float2*>(out + (size_t)row * DIM + col) = v0;
            *reinterpret_cast<float2*>(out + (size_t)(row + 8) * DIM + col) = v1;
        }
    }
}

extern "C" void kernel_launch(void* const* d_in, const int* in_sizes, int n_in,
                              void* d_out, int out_size) {
    const float* x  = (const float*)d_in[0];   // (4, 2048, 512) fp32
    const float* Wc = (const float*)d_in[1];   // (1024, 512) fp32
    float* out = (float*)d_out;                // (4, 2048, 512) fp32

    // one-time side resources (host objects; created on first call outside capture)
    static cudaStream_t s2 = nullptr;
    static cudaEvent_t ev_fork = nullptr, ev_join = nullptr;
    if (s2 == nullptr) {
        cudaStreamCreateWithFlags(&s2, cudaStreamNonBlocking);
        cudaEventCreateWithFlags(&ev_fork, cudaEventDisableTiming);
        cudaEventCreateWithFlags(&ev_join, cudaEventDisableTiming);
    }

    const size_t attn_smem = (size_t)(SROWS * TP2 + QT * SP) * sizeof(float); // 112,640 B
    cudaFuncSetAttribute(attn_kernel, cudaFuncAttributeMaxDynamicSharedMemorySize,
                         (int)attn_smem);
    const size_t gemm_smem = (size_t)(NSTAGE * STFH) * sizeof(__half);  // 81,920 B
    cudaFuncSetAttribute(gemm_mma, cudaFuncAttributeMaxDynamicSharedMemorySize,
                         (int)gemm_smem);

    // fork: Wc transpose (tiny, 0 smem) overlaps with attention
    cudaEventRecord(ev_fork, 0);
    cudaStreamWaitEvent(s2, ev_fork, 0);
    convw_kernel<<<512, 256, 0, s2>>>(Wc);
    cudaEventRecord(ev_join, s2);

    attn_kernel<<<BATCH * (SEQ / QT), 256, attn_smem>>>(x);

    // join: gemm consumes g_hwt, g_hc, g_hx
    cudaStreamWaitEvent(0, ev_join, 0);
    dim3 grid(DIM / GN, (BATCH * SEQ) / GM);   // (4, 64)
    gemm_mma<<<grid, 256, gemm_smem>>>(out);
}

// round 17
// speedup vs baseline: 1.4447x; 1.0121x over previous
#include <cuda_runtime.h>
#include <cuda_fp16.h>
#include <cstdint>
#include <math.h>

// ---------------- problem constants ----------------
#define BATCH 4
#define SEQ   2048
#define DIM   512
#define WIN   64
#define QT    32

// attention smem layout (D processed in 2 chunks of 256)
#define DC    256
#define TP2   260             // tile row pitch (floats)
#define SROWS 96
#define SP    100             // score row pitch

// gemm tiling (mma.sync fp16 m16n8k16), fused K=1024
#define GM 128
#define GN 128
#define KC 32
#define NCHUNK (1024 / KC)    // 32
#define APH 40                // A smem pitch in halves
#define BPH 40                // B smem pitch in halves (n-major)
#define AFLH (GM * APH)       // 5120 halves
#define BFLH (GN * BPH)       // 5120 halves
#define STFH (AFLH + BFLH)    // 10240 halves = 20480 B per stage
#define NSTAGE 4

typedef unsigned long long u64t;

// device scratch (no cudaMalloc allowed)
__device__ __half g_hc[BATCH * SEQ * DIM];         // context, fp16
__device__ __half g_hx[BATCH * SEQ * DIM];         // x, fp16 (written by attention)
__device__ __half g_hwt[DIM * 1024];               // Wc transposed: [n][k] fp16

__device__ __forceinline__ uint32_t smem_u32(const void* p) {
    uint32_t a;
    asm("{ .reg .u64 t; cvta.to.shared.u64 t, %1; cvt.u32.u64 %0, t; }"
        : "=r"(a) : "l"(p));
    return a;
}
__device__ __forceinline__ void cpa16(uint32_t d, const void* s) {
    asm volatile("cp.async.cg.shared.global [%0], [%1], 16;" :: "r"(d), "l"(s));
}
__device__ __forceinline__ void ldsm_x4(uint32_t& r0, uint32_t& r1,
                                        uint32_t& r2, uint32_t& r3, uint32_t addr) {
    asm volatile("ldmatrix.sync.aligned.m8n8.x4.shared.b16 {%0,%1,%2,%3}, [%4];"
                 : "=r"(r0), "=r"(r1), "=r"(r2), "=r"(r3) : "r"(addr));
}
// packed dual-fp32 FMA: acc(pair) += a(pair) * b(pair)
#define FMA2(acc, a, b) \
    asm("fma.rn.f32x2 %0, %1, %2, %0;" : "+l"(acc) : "l"(a), "l"(b))
#define PACK_DUP(p, bits) \
    asm("mov.b64 %0, {%1, %1};" : "=l"(p) : "r"(bits))
__device__ __forceinline__ float2 unpack2(u64t p) {
    uint32_t lo, hi;
    asm("mov.b64 {%0, %1}, %2;" : "=r"(lo), "=r"(hi) : "l"(p));
    return make_float2(__uint_as_float(lo), __uint_as_float(hi));
}

extern __shared__ float sm_dyn[];

// ---------------------------------------------------------------------------
// Wc convert+transpose, tiled (R15, measured). grid 512, block 256.
// ---------------------------------------------------------------------------
__global__ __launch_bounds__(256) void convw_kernel(const float* __restrict__ Wc) {
    __shared__ float t[32][33];
    const int tx = threadIdx.x & 31;
    const int ty = threadIdx.x >> 5;
    const int n0 = (blockIdx.x & 15) * 32;
    const int k0 = (blockIdx.x >> 4) * 32;
#pragma unroll
    for (int i = 0; i < 4; i++)
        t[ty + 8 * i][tx] = Wc[(size_t)(k0 + ty + 8 * i) * DIM + n0 + tx];
    __syncthreads();
#pragma unroll
    for (int i = 0; i < 4; i++)
        g_hwt[(size_t)(n0 + ty + 8 * i) * 1024 + k0 + tx] =
            __float2half_rn(t[tx][ty + 8 * i]);
}

// ---------------------------------------------------------------------------
// Attention: 256 CTAs, 256 threads, QT=32, 2 CTAs/SM.
// Phases 1 & 3 use packed f32x2 FMA (halves FMA-pipe instruction count,
// exact fp32 arithmetic). Structure otherwise identical to R15.
// ---------------------------------------------------------------------------
__global__ __launch_bounds__(256, 2) void attn_kernel(const float* __restrict__ x) {
    float* tile = sm_dyn;                 // [96][TP2]
    float* S    = sm_dyn + SROWS * TP2;   // [32][SP]

    const int tid = threadIdx.x;
    const int b   = blockIdx.x >> 6;
    const int qs  = (blockIdx.x & 63) * QT;
    const float* xb = x + (size_t)b * SEQ * DIM;

    const int ty = tid >> 5;
    const int tx = tid & 31;

    auto load_tile = [&](int d0) {
#pragma unroll 8
        for (int p = 0; p < 24; p++) {
            const int idx = tid + 256 * p;
            const int r   = idx >> 6;
            const int c4  = (idx & 63) << 2;
            const int gr  = qs - WIN + r;
            float4 v = make_float4(0.f, 0.f, 0.f, 0.f);
            if (gr >= 0)
                v = *reinterpret_cast<const float4*>(xb + (size_t)gr * DIM + d0 + c4);
            *reinterpret_cast<float4*>(tile + r * TP2 + c4) = v;
        }
    };

    // ---- phase 1 (+ hx conversion of query rows), f32x2 ----
    u64t sa2[4][3];
#pragma unroll
    for (int i = 0; i < 4; i++)
#pragma unroll
        for (int j = 0; j < 3; j++) sa2[i][j] = 0ull;

#pragma unroll
    for (int ch = 0; ch < 2; ch++) {
        if (ch) __syncthreads();
        load_tile(ch * DC);
        __syncthreads();

        // convert tile rows 64..95 (this CTA's query rows) -> g_hx
#pragma unroll
        for (int p = 0; p < 8; p++) {
            const int idx = tid + 256 * p;
            const int r   = idx >> 6;
            const int c4  = (idx & 63) << 2;
            float4 v = *reinterpret_cast<const float4*>(tile + (WIN + r) * TP2 + c4);
            __half2 h0 = __floats2half2_rn(v.x, v.y);
            __half2 h1 = __floats2half2_rn(v.z, v.w);
            uint2 uu;
            uu.x = *reinterpret_cast<uint32_t*>(&h0);
            uu.y = *reinterpret_cast<uint32_t*>(&h1);
            *reinterpret_cast<uint2*>(
                g_hx + ((size_t)(b * SEQ + qs + r) * DIM + ch * DC + c4)) = uu;
        }

        const float* q0 = tile + (WIN + 4 * ty) * TP2;
        const float* k0 = tile + tx * TP2;
#pragma unroll 2
        for (int d = 0; d < DC; d += 4) {
            ulonglong2 q2[4], k2[3];
#pragma unroll
            for (int ii = 0; ii < 4; ii++)
                q2[ii] = *reinterpret_cast<const ulonglong2*>(q0 + ii * TP2 + d);
#pragma unroll
            for (int jj = 0; jj < 3; jj++)
                k2[jj] = *reinterpret_cast<const ulonglong2*>(k0 + jj * 32 * TP2 + d);
#pragma unroll
            for (int ii = 0; ii < 4; ii++)
#pragma unroll
                for (int jj = 0; jj < 3; jj++) {
                    FMA2(sa2[ii][jj], q2[ii].x, k2[jj].x);
                    FMA2(sa2[ii][jj], q2[ii].y, k2[jj].y);
                }
        }
    }
#pragma unroll
    for (int ii = 0; ii < 4; ii++)
#pragma unroll
        for (int jj = 0; jj < 3; jj++) {
            float2 v = unpack2(sa2[ii][jj]);
            S[(4 * ty + ii) * SP + tx + 32 * jj] = v.x + v.y;
        }
    __syncthreads();

    // ---- phase 2: band softmax -> dense alpha (unchanged) ----
    {
        const int i = tid >> 3;
        const int g = tid & 7;
        float* srow = S + i * SP;
        float m = -1e30f;
        float vals[8];
#pragma unroll
        for (int w8 = 0; w8 < 8; w8++) {
            vals[w8] = srow[i + g + 8 * w8];
            m = fmaxf(m, vals[w8]);
        }
        m = fmaxf(m, __shfl_xor_sync(0xffffffffu, m, 1));
        m = fmaxf(m, __shfl_xor_sync(0xffffffffu, m, 2));
        m = fmaxf(m, __shfl_xor_sync(0xffffffffu, m, 4));
        float s = 0.f;
#pragma unroll
        for (int w8 = 0; w8 < 8; w8++) s += __expf(vals[w8] - m);
        s += __shfl_xor_sync(0xffffffffu, s, 1);
        s += __shfl_xor_sync(0xffffffffu, s, 2);
        s += __shfl_xor_sync(0xffffffffu, s, 4);
        const float inv = 1.f / s;
        __syncwarp();
#pragma unroll
        for (int jj = 0; jj < 12; jj++) {
            const int j = g * 12 + jj;
            float v = 0.f;
            if (j >= i && j < i + WIN) v = __expf(srow[j] - m) * inv;
            srow[j] = v;
        }
    }

    // ---- phase 3: chunk 1 first (resident), then chunk 0; f32x2; fp16 out ----
    const float* arow = S + 4 * ty * SP;
#pragma unroll
    for (int pass = 0; pass < 2; pass++) {
        const int ch = 1 - pass;
        __syncthreads();
        if (pass == 1) {
            load_tile(0);
            __syncthreads();
        }

        u64t cac2[4][4];   // 4 q-rows x 4 pairs (8 d-cols)
#pragma unroll
        for (int i = 0; i < 4; i++)
#pragma unroll
            for (int p = 0; p < 4; p++) cac2[i][p] = 0ull;

        for (int j = 0; j < 68; j++) {
            const int jj = 4 * ty + j;
            u64t ap[4];
#pragma unroll
            for (int ii = 0; ii < 4; ii++) {
                const uint32_t bits = __float_as_uint(arow[ii * SP + jj]);
                PACK_DUP(ap[ii], bits);
            }
            const float* kr = tile + jj * TP2 + 4 * tx;
            ulonglong2 kv0 = *reinterpret_cast<const ulonglong2*>(kr);
            ulonglong2 kv1 = *reinterpret_cast<const ulonglong2*>(kr + 128);
#pragma unroll
            for (int ii = 0; ii < 4; ii++) {
                FMA2(cac2[ii][0], ap[ii], kv0.x);
                FMA2(cac2[ii][1], ap[ii], kv0.y);
                FMA2(cac2[ii][2], ap[ii], kv1.x);
                FMA2(cac2[ii][3], ap[ii], kv1.y);
            }
        }
#pragma unroll
        for (int ii = 0; ii < 4; ii++) {
            __half* crow = g_hc + ((size_t)(b * SEQ + qs + 4 * ty + ii)) * DIM
                         + ch * DC + 4 * tx;
#pragma unroll
            for (int q = 0; q < 2; q++) {
                float2 lo = unpack2(cac2[ii][2 * q]);
                float2 hi = unpack2(cac2[ii][2 * q + 1]);
                __half2 h0 = __floats2half2_rn(lo.x, lo.y);
                __half2 h1 = __floats2half2_rn(hi.x, hi.y);
                uint2 uu;
                uu.x = *reinterpret_cast<uint32_t*>(&h0);
                uu.y = *reinterpret_cast<uint32_t*>(&h1);
                *reinterpret_cast<uint2*>(crow + 128 * q) = uu;
            }
        }
    }
}

// ---------------------------------------------------------------------------
// Output head (R14/R15, measured ~43us): out = sigmoid([c | x] @ Wc), fp16 mma.
// ---------------------------------------------------------------------------
__device__ __forceinline__ void mma_f16(float* c, uint32_t a0, uint32_t a1,
                                        uint32_t a2, uint32_t a3,
                                        uint32_t b0, uint32_t b1) {
    asm volatile(
        "mma.sync.aligned.m16n8k16.row.col.f32.f16.f16.f32 "
        "{%0,%1,%2,%3}, {%4,%5,%6,%7}, {%8,%9}, {%0,%1,%2,%3};"
        : "+f"(c[0]), "+f"(c[1]), "+f"(c[2]), "+f"(c[3])
        : "r"(a0), "r"(a1), "r"(a2), "r"(a3), "r"(b0), "r"(b1));
}

__device__ __forceinline__ void issue_chunk(int c, int bm, int bn, int tid) {
    __half* Ad = reinterpret_cast<__half*>(sm_dyn) + (c & 3) * STFH;
    __half* Bd = Ad + AFLH;
    const __half* Asrc = (c < 16) ? g_hc : g_hx;
    const int koff = (c < 16) ? c * KC : c * KC - 512;
#pragma unroll
    for (int p = 0; p < 2; p++) {
        const int idx = tid + 256 * p;
        const int r   = idx >> 2;
        const int seg = idx & 3;
        cpa16(smem_u32(Ad + r * APH + seg * 8),
              Asrc + (size_t)(bm + r) * DIM + koff + seg * 8);
    }
#pragma unroll
    for (int p = 0; p < 2; p++) {
        const int idx = tid + 256 * p;
        const int n   = idx >> 2;
        const int seg = idx & 3;
        cpa16(smem_u32(Bd + n * BPH + seg * 8),
              g_hwt + (size_t)(bn + n) * 1024 + c * KC + seg * 8);
    }
    asm volatile("cp.async.commit_group;" ::: "memory");
}

__global__ __launch_bounds__(256, 2) void gemm_mma(float* __restrict__ out) {
    const int tid  = threadIdx.x;
    const int wid  = tid >> 5;
    const int lane = tid & 31;
    const int gid  = lane >> 2;
    const int tig  = lane & 3;
    const int wm   = wid & 1;
    const int wn   = wid >> 1;
    const int bm   = blockIdx.y * GM;
    const int bn   = blockIdx.x * GN;

    float acc[4][4][4];
#pragma unroll
    for (int i = 0; i < 4; i++)
#pragma unroll
        for (int j = 0; j < 4; j++)
#pragma unroll
            for (int k = 0; k < 4; k++) acc[i][j][k] = 0.f;

    const uint32_t sm_base = smem_u32(sm_dyn);
    const uint32_t a_off =
        (uint32_t)(((wm * 64 + (lane & 15)) * APH + ((lane >> 4) & 1) * 8) * 2);
    const uint32_t b_off =
        (uint32_t)(((wn * 32 + (lane & 7) + ((lane >> 4) & 1) * 8) * BPH
                    + ((lane >> 3) & 1) * 8) * 2);

    issue_chunk(0, bm, bn, tid);
    issue_chunk(1, bm, bn, tid);
    issue_chunk(2, bm, bn, tid);

    for (int c = 0; c < NCHUNK; c++) {
        if (c <= NCHUNK - 3)
            asm volatile("cp.async.wait_group 2;" ::: "memory");
        else if (c == NCHUNK - 2)
            asm volatile("cp.async.wait_group 1;" ::: "memory");
        else
            asm volatile("cp.async.wait_group 0;" ::: "memory");
        __syncthreads();
        if (c + 3 < NCHUNK) issue_chunk(c + 3, bm, bn, tid);

        const uint32_t As_addr = sm_base + (uint32_t)((c & 3) * STFH * 2);
        const uint32_t Bs_addr = As_addr + (uint32_t)(AFLH * 2);
#pragma unroll
        for (int kk = 0; kk < KC; kk += 16) {
            uint32_t a[4][4], bb[2][4];
#pragma unroll
            for (int ma = 0; ma < 4; ma++)
                ldsm_x4(a[ma][0], a[ma][1], a[ma][2], a[ma][3],
                        As_addr + a_off + (uint32_t)((ma * 16 * APH + kk) * 2));
#pragma unroll
            for (int p = 0; p < 2; p++)
                ldsm_x4(bb[p][0], bb[p][1], bb[p][2], bb[p][3],
                        Bs_addr + b_off + (uint32_t)((p * 16 * BPH + kk) * 2));
#pragma unroll
            for (int ma = 0; ma < 4; ma++)
#pragma unroll
                for (int na = 0; na < 4; na++)
                    mma_f16(acc[ma][na], a[ma][0], a[ma][1], a[ma][2], a[ma][3],
                            bb[na >> 1][(na & 1) * 2], bb[na >> 1][(na & 1) * 2 + 1]);
        }
    }

    // ---- epilogue: sigmoid + store ----
#pragma unroll
    for (int ma = 0; ma < 4; ma++) {
#pragma unroll
        for (int na = 0; na < 4; na++) {
            const int row = bm + wm * 64 + ma * 16 + gid;
            const int col = bn + wn * 32 + na * 8 + 2 * tig;
            float2 v0, v1;
            v0.x = 1.f / (1.f + __expf(-acc[ma][na][0]));
            v0.y = 1.f / (1.f + __expf(-acc[ma][na][1]));
            v1.x = 1.f / (1.f + __expf(-acc[ma][na][2]));
            v1.y = 1.f / (1.f + __expf(-acc[ma][na][3]));
            *reinterpret_cast<float2*>(out + (size_t)row * DIM + col) = v0;
            *reinterpret_cast<float2*>(out + (size_t)(row + 8) * DIM + col) = v1;
        }
    }
}

extern "C" void kernel_launch(void* const* d_in, const int* in_sizes, int n_in,
                              void* d_out, int out_size) {
    const float* x  = (const float*)d_in[0];   // (4, 2048, 512) fp32
    const float* Wc = (const float*)d_in[1];   // (1024, 512) fp32
    float* out = (float*)d_out;                // (4, 2048, 512) fp32

    static cudaStream_t s2 = nullptr;
    static cudaEvent_t ev_fork = nullptr, ev_join = nullptr;
    if (s2 == nullptr) {
        cudaStreamCreateWithFlags(&s2, cudaStreamNonBlocking);
        cudaEventCreateWithFlags(&ev_fork, cudaEventDisableTiming);
        cudaEventCreateWithFlags(&ev_join, cudaEventDisableTiming);
    }

    const size_t attn_smem = (size_t)(SROWS * TP2 + QT * SP) * sizeof(float); // 112,640 B
    cudaFuncSetAttribute(attn_kernel, cudaFuncAttributeMaxDynamicSharedMemorySize,
                         (int)attn_smem);
    const size_t gemm_smem = (size_t)(NSTAGE * STFH) * sizeof(__half);  // 81,920 B
    cudaFuncSetAttribute(gemm_mma, cudaFuncAttributeMaxDynamicSharedMemorySize,
                         (int)gemm_smem);

    cudaEventRecord(ev_fork, 0);
    cudaStreamWaitEvent(s2, ev_fork, 0);
    convw_kernel<<<512, 256, 0, s2>>>(Wc);
    cudaEventRecord(ev_join, s2);

    attn_kernel<<<BATCH * (SEQ / QT), 256, attn_smem>>>(x);

    cudaStreamWaitEvent(0, ev_join, 0);
    dim3 grid(DIM / GN, (BATCH * SEQ) / GM);   // (4, 64)
    gemm_mma<<<grid, 256, gemm_smem>>>(out);
}